// round 6
// baseline (speedup 1.0000x reference)
#include <cuda_runtime.h>
#include <cstdint>

// Problem constants
#define N_TOK 16384
#define DIM   1024
#define HID   4096
#define HHALF 2048
#define NEXP  8
#define EPSLN 1e-5f

// CTA tile
#define BM 128
#define BN 256
#define BSTRD 264     // BN + 8 pad, conflict-free B frag reads

// ---------------- scratch (static device globals) -----------------------------
__device__ float g_xn [(size_t)N_TOK * DIM];
__device__ float g_xnl[(size_t)N_TOK * DIM];
__device__ float g_hr [(size_t)N_TOK * HHALF];
__device__ float g_h  [(size_t)(2 * N_TOK) * HID];
__device__ float g_y  [(size_t)(2 * N_TOK) * DIM];
__device__ float g_w1h[(size_t)DIM * HHALF];
__device__ float g_w1l[(size_t)DIM * HHALF];
__device__ int   g_cnt[NEXP];
__device__ int   g_off[NEXP];
__device__ int   g_fill[NEXP];
__device__ int   g_e12[N_TOK];
__device__ float g_g1[N_TOK];
__device__ float g_g2[N_TOK];
__device__ int   g_list[2 * N_TOK];
__device__ int   g_s1[N_TOK];
__device__ int   g_s2[N_TOK];

// ---------------- helpers ------------------------------------------------------
__device__ __forceinline__ uint32_t smem_u32(const void* p) {
    uint32_t a;
    asm("{ .reg .u64 t; cvta.to.shared.u64 t, %1; cvt.u32.u64 %0, t; }" : "=r"(a) : "l"(p));
    return a;
}
__device__ __forceinline__ float rtf32(float x) {
    float r; asm("cvt.rna.tf32.f32 %0, %1;" : "=f"(r) : "f"(x)); return r;
}
#define CP16(dst, src) \
    asm volatile("cp.async.cg.shared.global [%0], [%1], 16;" :: "r"(dst), "l"(src) : "memory")
#define CP_COMMIT() asm volatile("cp.async.commit_group;" ::: "memory")
#define CP_WAIT1()  asm volatile("cp.async.wait_group 1;" ::: "memory")
#define CP_WAIT0()  asm volatile("cp.async.wait_group 0;" ::: "memory")

__device__ __forceinline__ void mma8(float c[4], const uint32_t a[4], const uint32_t b[2]) {
    asm volatile(
        "mma.sync.aligned.m16n8k8.row.col.f32.tf32.tf32.f32 "
        "{%0,%1,%2,%3}, {%4,%5,%6,%7}, {%8,%9}, {%0,%1,%2,%3};"
        : "+f"(c[0]), "+f"(c[1]), "+f"(c[2]), "+f"(c[3])
        : "r"(a[0]), "r"(a[1]), "r"(a[2]), "r"(a[3]), "r"(b[0]), "r"(b[1]));
}

// ---------------- LayerNorm: writes tf32 hi + lo -------------------------------
__global__ void ln_kernel(const float* __restrict__ x,
                          const float* __restrict__ gam,
                          const float* __restrict__ bet) {
    int row = blockIdx.x;
    const float* xr = x + (size_t)row * DIM;
    float s = 0.f, ss = 0.f;
    for (int i = threadIdx.x; i < DIM; i += 256) {
        float v = xr[i];
        s += v; ss += v * v;
    }
    __shared__ float sh[64];
    for (int o = 16; o; o >>= 1) {
        s  += __shfl_xor_sync(0xFFFFFFFFu, s,  o);
        ss += __shfl_xor_sync(0xFFFFFFFFu, ss, o);
    }
    int w = threadIdx.x >> 5, l = threadIdx.x & 31;
    if (l == 0) { sh[w] = s; sh[w + 32] = ss; }
    __syncthreads();
    if (w == 0) {
        s  = (l < 8) ? sh[l] : 0.f;
        ss = (l < 8) ? sh[l + 32] : 0.f;
        for (int o = 4; o; o >>= 1) {
            s  += __shfl_xor_sync(0xFFFFFFFFu, s,  o);
            ss += __shfl_xor_sync(0xFFFFFFFFu, ss, o);
        }
        if (l == 0) { sh[0] = s; sh[1] = ss; }
    }
    __syncthreads();
    float mu  = sh[0] * (1.0f / DIM);
    float var = sh[1] * (1.0f / DIM) - mu * mu;
    float r   = rsqrtf(var + EPSLN);
    for (int i = threadIdx.x; i < DIM; i += 256) {
        float v = (xr[i] - mu) * r * gam[i] + bet[i];
        float h = rtf32(v);
        g_xn [(size_t)row * DIM + i] = h;
        g_xnl[(size_t)row * DIM + i] = rtf32(v - h);
    }
}

// ---------------- weight prep (router only) ------------------------------------
__global__ void split_copy(const float* __restrict__ in,
                           float* __restrict__ hi, float* __restrict__ lo) {
    size_t i = (size_t)(blockIdx.x * 256 + threadIdx.x) * 4;
    float4 v = *(const float4*)(in + i);
    float4 h, l;
    h.x = rtf32(v.x); l.x = rtf32(v.x - h.x);
    h.y = rtf32(v.y); l.y = rtf32(v.y - h.y);
    h.z = rtf32(v.z); l.z = rtf32(v.z - h.z);
    h.w = rtf32(v.w); l.w = rtf32(v.w - h.w);
    *(float4*)(hi + i) = h;
    *(float4*)(lo + i) = l;
}

// ---------------- Router logits + softmax top-2 + gates ------------------------
__global__ void router_kernel(const float* __restrict__ w2,
                              const float* __restrict__ b2) {
    int warp = threadIdx.x >> 5, lane = threadIdx.x & 31;
    int t = blockIdx.x * 8 + warp;
    const float* hrow = g_hr + (size_t)t * HHALF;
    float acc[NEXP] = {};
    for (int i = lane; i < HHALF; i += 32) {
        float v = hrow[i];
        const float4* wp = (const float4*)(w2 + i * NEXP);
        float4 w0 = __ldg(wp), w1 = __ldg(wp + 1);
        acc[0] += v * w0.x; acc[1] += v * w0.y; acc[2] += v * w0.z; acc[3] += v * w0.w;
        acc[4] += v * w1.x; acc[5] += v * w1.y; acc[6] += v * w1.z; acc[7] += v * w1.w;
    }
    for (int o = 16; o; o >>= 1)
#pragma unroll
        for (int e = 0; e < NEXP; e++)
            acc[e] += __shfl_xor_sync(0xFFFFFFFFu, acc[e], o);
    if (lane == 0) {
        float l[NEXP];
#pragma unroll
        for (int e = 0; e < NEXP; e++) l[e] = acc[e] + b2[e];
        int e1 = 0;
        for (int e = 1; e < NEXP; e++) if (l[e] > l[e1]) e1 = e;
        int e2 = -1;
        for (int e = 0; e < NEXP; e++) {
            if (e == e1) continue;
            if (e2 < 0 || l[e] > l[e2]) e2 = e;
        }
        float ed  = expf(l[e2] - l[e1]);
        float inv = 1.f / (1.f + ed);
        g_e12[t] = e1 | (e2 << 8);
        g_g1[t] = inv;
        g_g2[t] = ed * inv;
        atomicAdd(&g_cnt[e1], 1);
        atomicAdd(&g_cnt[e2], 1);
    }
}

__global__ void zero_cnt_kernel() {
    if (threadIdx.x < NEXP) g_cnt[threadIdx.x] = 0;
}
__global__ void scan_kernel() {
    if (threadIdx.x == 0) {
        int s = 0;
        for (int e = 0; e < NEXP; e++) { g_off[e] = s; s += g_cnt[e]; g_fill[e] = 0; }
    }
}
__global__ void place_kernel() {
    int t = blockIdx.x * 256 + threadIdx.x;
    if (t >= N_TOK) return;
    int e12 = g_e12[t];
    int e1 = e12 & 0xFF, e2 = e12 >> 8;
    int s1 = g_off[e1] + atomicAdd(&g_fill[e1], 1);
    g_list[s1] = t; g_s1[t] = s1;
    int s2 = g_off[e2] + atomicAdd(&g_fill[e2], 1);
    g_list[s2] = t; g_s2[t] = s2;
}

// ---------------- final combine: out = x + g1*y[s1] + g2*y[s2] ------------------
__global__ void combine_kernel(const float* __restrict__ x, float* __restrict__ out) {
    int t = blockIdx.x;
    int s1 = g_s1[t], s2 = g_s2[t];
    float a = g_g1[t], b = g_g2[t];
    const float4* xr = (const float4*)(x   + (size_t)t  * DIM);
    const float4* y1 = (const float4*)(g_y + (size_t)s1 * DIM);
    const float4* y2 = (const float4*)(g_y + (size_t)s2 * DIM);
    float4* o = (float4*)(out + (size_t)t * DIM);
    int i = threadIdx.x;
    float4 xv = xr[i], v1 = y1[i], v2 = y2[i];
    float4 r;
    r.x = xv.x + a * v1.x + b * v2.x;
    r.y = xv.y + a * v1.y + b * v2.y;
    r.z = xv.z + a * v1.z + b * v2.z;
    r.w = xv.w + a * v1.w + b * v2.w;
    o[i] = r;
}

// ---------------- tf32 mma.sync GEMM (128x256 CTA, 64x64 warp tiles) ------------
// 2-stage cp.async pipeline, 2 CTAs/SM co-resident (smem ~104KB each).
// MODE 0: g_hr = relu(split-tf32(xn @ r_w1) + b)       M=16384 N=2048 K=1024
// MODE 1: g_h  = rtf32(relu(gather(xn) @ e_w1 + b))    M=cnt   N=4096 K=1024
// MODE 2: g_y  = g_h @ e_w2 + b   (compact rows)       M=cnt   N=1024 K=4096
template <int MODE>
__global__ void __launch_bounds__(256, 2)
moe_mma(const float* __restrict__ Wbase, const float* __restrict__ Wlbase,
        const float* __restrict__ bias) {
    constexpr bool SPLIT = (MODE == 0);
    constexpr int Kd  = (MODE == 2) ? HID : DIM;
    constexpr int Nd  = (MODE == 0) ? HHALF : (MODE == 1) ? HID : DIM;
    constexpr int BKC = SPLIT ? 16 : 32;
    constexpr int NC  = Kd / BKC;
    constexpr int AST = BKC + 4;
    constexpr int ASZ = BM * AST;
    constexpr int BSZ = BKC * BSTRD;
    constexpr int STG = (SPLIT ? 2 : 1) * (ASZ + BSZ);
    constexpr int AJ  = BKC / 8;
    constexpr int BJ  = BKC / 4;

    int bm = blockIdx.y * BM, bn = blockIdx.x * BN;
    int e = 0, cnt = N_TOK, base = 0;
    if (MODE != 0) {
        e = blockIdx.z;
        cnt = g_cnt[e];
        if (bm >= cnt) return;
        base = g_off[e];
    }
    const float* Wh = (MODE == 0) ? Wbase
                    : (MODE == 1) ? Wbase + (size_t)e * DIM * HID
                                  : Wbase + (size_t)e * HID * DIM;
    const float* Wl = Wlbase;
    const float* bp = bias + ((MODE == 0) ? 0 : (MODE == 1) ? e * HID : e * DIM);

    extern __shared__ float sm[];
    uint32_t smb = smem_u32(sm);

    int tid = threadIdx.x, lane = tid & 31, wid = tid >> 5;
    int wm = (wid >> 2) * 64, wn = (wid & 3) * 64;

    // ---- per-thread load slots ----
    const float* ah[AJ];
    const float* al[AJ];
    const float* bh[BJ];
    const float* bl[BJ];
    uint32_t adst[AJ], bdst[BJ];
#pragma unroll
    for (int j = 0; j < AJ; j++) {
        int id = tid + 256 * j;
        int row = id / (BKC / 4), c4 = id % (BKC / 4);
        adst[j] = (uint32_t)row * (AST * 4) + c4 * 16;
        int r = bm + row;
        if (MODE == 1) {
            int rr = (r < cnt) ? r : cnt - 1;
            ah[j] = g_xn + (size_t)g_list[base + rr] * DIM + c4 * 4;
        } else if (MODE == 2) {
            int rr = (r < cnt) ? r : cnt - 1;
            ah[j] = g_h + (size_t)(base + rr) * HID + c4 * 4;
        } else {
            ah[j] = g_xn  + (size_t)r * DIM + c4 * 4;
            al[j] = g_xnl + (size_t)r * DIM + c4 * 4;
        }
    }
#pragma unroll
    for (int j = 0; j < BJ; j++) {
        int id = tid + 256 * j;
        int kr = id >> 6, c = id & 63;
        bdst[j] = (uint32_t)kr * (BSTRD * 4) + c * 16;
        bh[j] = Wh + (size_t)kr * Nd + bn + c * 4;
        if (SPLIT) bl[j] = Wl + (size_t)kr * Nd + bn + c * 4;
    }

    auto load = [&](int i, int st) {
        uint32_t s0 = smb + (uint32_t)st * STG * 4;
        uint32_t b0 = s0 + (SPLIT ? 2u : 1u) * ASZ * 4;
        int ko = i * BKC;
        size_t bko = (size_t)ko * Nd;
#pragma unroll
        for (int j = 0; j < AJ; j++) {
            CP16(s0 + adst[j], ah[j] + ko);
            if (SPLIT) CP16(s0 + ASZ * 4 + adst[j], al[j] + ko);
        }
#pragma unroll
        for (int j = 0; j < BJ; j++) {
            CP16(b0 + bdst[j], bh[j] + bko);
            if (SPLIT) CP16(b0 + BSZ * 4 + bdst[j], bl[j] + bko);
        }
        CP_COMMIT();
    };

    float c[4][8][4] = {};
    load(0, 0);
    load(1, 1);

    int lr = lane >> 2, lc = lane & 3;
    for (int i = 0; i < NC; i++) {
        int st = i & 1;
        if (i + 1 < NC) { CP_WAIT1(); } else { CP_WAIT0(); }
        __syncthreads();

        const uint32_t* Au = (const uint32_t*)(sm + st * STG);
        const uint32_t* Bu = Au + (SPLIT ? 2 : 1) * ASZ;
#pragma unroll
        for (int ks = 0; ks < BKC / 8; ks++) {
            uint32_t a[4][4], b[8][2];
#pragma unroll
            for (int mt = 0; mt < 4; mt++) {
                const uint32_t* ap = Au + (wm + mt * 16 + lr) * AST + ks * 8 + lc;
                a[mt][0] = ap[0];
                a[mt][1] = ap[8 * AST];
                a[mt][2] = ap[4];
                a[mt][3] = ap[8 * AST + 4];
            }
#pragma unroll
            for (int nt = 0; nt < 8; nt++) {
                const uint32_t* bpp = Bu + (ks * 8 + lc) * BSTRD + wn + nt * 8 + lr;
                b[nt][0] = bpp[0];
                b[nt][1] = bpp[4 * BSTRD];
            }
#pragma unroll
            for (int mt = 0; mt < 4; mt++)
#pragma unroll
                for (int nt = 0; nt < 8; nt++)
                    mma8(c[mt][nt], a[mt], b[nt]);
            if (SPLIT) {
                // hi * lo
                uint32_t t2[8][2];
#pragma unroll
                for (int nt = 0; nt < 8; nt++) {
                    const uint32_t* bpp = Bu + BSZ + (ks * 8 + lc) * BSTRD + wn + nt * 8 + lr;
                    t2[nt][0] = bpp[0];
                    t2[nt][1] = bpp[4 * BSTRD];
                }
#pragma unroll
                for (int mt = 0; mt < 4; mt++)
#pragma unroll
                    for (int nt = 0; nt < 8; nt++)
                        mma8(c[mt][nt], a[mt], t2[nt]);
                // lo * hi
                uint32_t a2[4][4];
#pragma unroll
                for (int mt = 0; mt < 4; mt++) {
                    const uint32_t* ap = Au + ASZ + (wm + mt * 16 + lr) * AST + ks * 8 + lc;
                    a2[mt][0] = ap[0];
                    a2[mt][1] = ap[8 * AST];
                    a2[mt][2] = ap[4];
                    a2[mt][3] = ap[8 * AST + 4];
                }
#pragma unroll
                for (int mt = 0; mt < 4; mt++)
#pragma unroll
                    for (int nt = 0; nt < 8; nt++)
                        mma8(c[mt][nt], a2[mt], b[nt]);
            }
        }
        __syncthreads();                      // all warps done reading stage st
        if (i + 2 < NC) load(i + 2, st);      // refill the stage just consumed
    }

    // ---------------- epilogue ----------------
#pragma unroll
    for (int mt = 0; mt < 4; mt++) {
#pragma unroll
        for (int half = 0; half < 2; half++) {
            int r = bm + wm + mt * 16 + lr + half * 8;
            if (MODE != 0 && r >= cnt) continue;
            float* row;
            if (MODE == 0)      row = g_hr + (size_t)r * HHALF;
            else if (MODE == 1) row = g_h  + (size_t)(base + r) * HID;
            else                row = g_y  + (size_t)(base + r) * DIM;
#pragma unroll
            for (int nt = 0; nt < 8; nt++) {
                int col = bn + wn + nt * 8 + lc * 2;
                float v0 = c[mt][nt][half * 2]     + bp[col];
                float v1 = c[mt][nt][half * 2 + 1] + bp[col + 1];
                float2 st2;
                if (MODE == 0) {
                    st2.x = fmaxf(v0, 0.f); st2.y = fmaxf(v1, 0.f);
                } else if (MODE == 1) {
                    st2.x = rtf32(fmaxf(v0, 0.f)); st2.y = rtf32(fmaxf(v1, 0.f));
                } else {
                    st2.x = v0; st2.y = v1;
                }
                *(float2*)(row + col) = st2;
            }
        }
    }
}

// ---------------- launch ---------------------------------------------------------
extern "C" void kernel_launch(void* const* d_in, const int* in_sizes, int n_in,
                              void* d_out, int out_size) {
    const float* x    = (const float*)d_in[0];
    const float* ln_g = (const float*)d_in[1];
    const float* ln_b = (const float*)d_in[2];
    const float* r_w1 = (const float*)d_in[3];
    const float* r_b1 = (const float*)d_in[4];
    const float* r_w2 = (const float*)d_in[5];
    const float* r_b2 = (const float*)d_in[6];
    const float* e_w1 = (const float*)d_in[7];
    const float* e_b1 = (const float*)d_in[8];
    const float* e_w2 = (const float*)d_in[9];
    const float* e_b2 = (const float*)d_in[10];
    float* out = (float*)d_out;

    // smem sizes (2-stage)
    const int SMEM_P = 2 * (BM * 36 + 32 * BSTRD) * 4;             // plain: 104448
    const int SMEM_S = 2 * (2 * (BM * 20) + 2 * (16 * BSTRD)) * 4; // split: 108544

    static int configured = 0;
    if (!configured) {
        cudaFuncSetAttribute(moe_mma<0>, cudaFuncAttributeMaxDynamicSharedMemorySize, SMEM_S);
        cudaFuncSetAttribute(moe_mma<1>, cudaFuncAttributeMaxDynamicSharedMemorySize, SMEM_P);
        cudaFuncSetAttribute(moe_mma<2>, cudaFuncAttributeMaxDynamicSharedMemorySize, SMEM_P);
        configured = 1;
    }

    zero_cnt_kernel<<<1, 32>>>();
    ln_kernel<<<N_TOK, 256>>>(x, ln_g, ln_b);

    // router weight split (tf32 hi/lo)
    float *w1h, *w1l;
    cudaGetSymbolAddress((void**)&w1h, g_w1h);
    cudaGetSymbolAddress((void**)&w1l, g_w1l);
    split_copy<<<(DIM * HHALF / 4) / 256, 256>>>(r_w1, w1h, w1l);

    // router path (split-tf32 GEMM -> logits -> top-2 -> dispatch lists)
    moe_mma<0><<<dim3(HHALF / BN, N_TOK / BM), 256, SMEM_S>>>(w1h, w1l, r_b1);
    router_kernel<<<N_TOK / 8, 256>>>(r_w2, r_b2);
    scan_kernel<<<1, 32>>>();
    place_kernel<<<N_TOK / 256, 256>>>();

    // expert path (raw fp32 weights; HW truncates to tf32)
    moe_mma<1><<<dim3(HID / BN, N_TOK / BM, NEXP), 256, SMEM_P>>>(e_w1, nullptr, e_b1);
    moe_mma<2><<<dim3(DIM / BN, N_TOK / BM, NEXP), 256, SMEM_P>>>(e_w2, nullptr, e_b2);

    // out = x + g1*y1 + g2*y2
    combine_kernel<<<N_TOK, 256>>>(x, out);
}

// round 7
// speedup vs baseline: 2.7057x; 2.7057x over previous
#include <cuda_runtime.h>
#include <cstdint>

// Problem constants
#define N_TOK 16384
#define DIM   1024
#define HID   4096
#define HHALF 2048
#define NEXP  8
#define EPSLN 1e-5f

// CTA tile
#define BM 128
#define BN 256
#define BSTRD 264     // BN + 8 pad, conflict-free B frag reads

// ---------------- scratch (static device globals) -----------------------------
__device__ float g_xn [(size_t)N_TOK * DIM];
__device__ float g_xnl[(size_t)N_TOK * DIM];
__device__ float g_hr [(size_t)N_TOK * HHALF];
__device__ float g_h  [(size_t)(2 * N_TOK) * HID];
__device__ float g_y  [(size_t)(2 * N_TOK) * DIM];
__device__ float g_w1h[(size_t)DIM * HHALF];
__device__ float g_w1l[(size_t)DIM * HHALF];
__device__ int   g_cnt[NEXP];
__device__ int   g_off[NEXP];
__device__ int   g_fill[NEXP];
__device__ int   g_e12[N_TOK];
__device__ float g_g1[N_TOK];
__device__ float g_g2[N_TOK];
__device__ int   g_list[2 * N_TOK];
__device__ int   g_s1[N_TOK];
__device__ int   g_s2[N_TOK];

// ---------------- helpers ------------------------------------------------------
__device__ __forceinline__ uint32_t smem_u32(const void* p) {
    uint32_t a;
    asm("{ .reg .u64 t; cvta.to.shared.u64 t, %1; cvt.u32.u64 %0, t; }" : "=r"(a) : "l"(p));
    return a;
}
__device__ __forceinline__ float rtf32(float x) {
    float r; asm("cvt.rna.tf32.f32 %0, %1;" : "=f"(r) : "f"(x)); return r;
}
#define CP16(dst, src) \
    asm volatile("cp.async.cg.shared.global [%0], [%1], 16;" :: "r"(dst), "l"(src) : "memory")
#define CP_COMMIT() asm volatile("cp.async.commit_group;" ::: "memory")
#define CP_WAIT1()  asm volatile("cp.async.wait_group 1;" ::: "memory")
#define CP_WAIT0()  asm volatile("cp.async.wait_group 0;" ::: "memory")

__device__ __forceinline__ void mma8(float c[4], const uint32_t a[4], const uint32_t b[2]) {
    asm volatile(
        "mma.sync.aligned.m16n8k8.row.col.f32.tf32.tf32.f32 "
        "{%0,%1,%2,%3}, {%4,%5,%6,%7}, {%8,%9}, {%0,%1,%2,%3};"
        : "+f"(c[0]), "+f"(c[1]), "+f"(c[2]), "+f"(c[3])
        : "r"(a[0]), "r"(a[1]), "r"(a[2]), "r"(a[3]), "r"(b[0]), "r"(b[1]));
}

// ---------------- LayerNorm: writes tf32 hi + lo -------------------------------
__global__ void ln_kernel(const float* __restrict__ x,
                          const float* __restrict__ gam,
                          const float* __restrict__ bet) {
    int row = blockIdx.x;
    const float* xr = x + (size_t)row * DIM;
    float s = 0.f, ss = 0.f;
    for (int i = threadIdx.x; i < DIM; i += 256) {
        float v = xr[i];
        s += v; ss += v * v;
    }
    __shared__ float sh[64];
    for (int o = 16; o; o >>= 1) {
        s  += __shfl_xor_sync(0xFFFFFFFFu, s,  o);
        ss += __shfl_xor_sync(0xFFFFFFFFu, ss, o);
    }
    int w = threadIdx.x >> 5, l = threadIdx.x & 31;
    if (l == 0) { sh[w] = s; sh[w + 32] = ss; }
    __syncthreads();
    if (w == 0) {
        s  = (l < 8) ? sh[l] : 0.f;
        ss = (l < 8) ? sh[l + 32] : 0.f;
        for (int o = 4; o; o >>= 1) {
            s  += __shfl_xor_sync(0xFFFFFFFFu, s,  o);
            ss += __shfl_xor_sync(0xFFFFFFFFu, ss, o);
        }
        if (l == 0) { sh[0] = s; sh[1] = ss; }
    }
    __syncthreads();
    float mu  = sh[0] * (1.0f / DIM);
    float var = sh[1] * (1.0f / DIM) - mu * mu;
    float r   = rsqrtf(var + EPSLN);
    for (int i = threadIdx.x; i < DIM; i += 256) {
        float v = (xr[i] - mu) * r * gam[i] + bet[i];
        float h = rtf32(v);
        g_xn [(size_t)row * DIM + i] = h;
        g_xnl[(size_t)row * DIM + i] = rtf32(v - h);
    }
}

// ---------------- weight prep (router only) ------------------------------------
__global__ void split_copy(const float* __restrict__ in,
                           float* __restrict__ hi, float* __restrict__ lo) {
    size_t i = (size_t)(blockIdx.x * 256 + threadIdx.x) * 4;
    float4 v = *(const float4*)(in + i);
    float4 h, l;
    h.x = rtf32(v.x); l.x = rtf32(v.x - h.x);
    h.y = rtf32(v.y); l.y = rtf32(v.y - h.y);
    h.z = rtf32(v.z); l.z = rtf32(v.z - h.z);
    h.w = rtf32(v.w); l.w = rtf32(v.w - h.w);
    *(float4*)(hi + i) = h;
    *(float4*)(lo + i) = l;
}

// ---------------- Router logits + softmax top-2 + gates ------------------------
__global__ void router_kernel(const float* __restrict__ w2,
                              const float* __restrict__ b2) {
    int warp = threadIdx.x >> 5, lane = threadIdx.x & 31;
    int t = blockIdx.x * 8 + warp;
    const float* hrow = g_hr + (size_t)t * HHALF;
    float acc[NEXP] = {};
    for (int i = lane; i < HHALF; i += 32) {
        float v = hrow[i];
        const float4* wp = (const float4*)(w2 + i * NEXP);
        float4 w0 = __ldg(wp), w1 = __ldg(wp + 1);
        acc[0] += v * w0.x; acc[1] += v * w0.y; acc[2] += v * w0.z; acc[3] += v * w0.w;
        acc[4] += v * w1.x; acc[5] += v * w1.y; acc[6] += v * w1.z; acc[7] += v * w1.w;
    }
    for (int o = 16; o; o >>= 1)
#pragma unroll
        for (int e = 0; e < NEXP; e++)
            acc[e] += __shfl_xor_sync(0xFFFFFFFFu, acc[e], o);
    if (lane == 0) {
        float l[NEXP];
#pragma unroll
        for (int e = 0; e < NEXP; e++) l[e] = acc[e] + b2[e];
        int e1 = 0;
        for (int e = 1; e < NEXP; e++) if (l[e] > l[e1]) e1 = e;
        int e2 = -1;
        for (int e = 0; e < NEXP; e++) {
            if (e == e1) continue;
            if (e2 < 0 || l[e] > l[e2]) e2 = e;
        }
        float ed  = expf(l[e2] - l[e1]);
        float inv = 1.f / (1.f + ed);
        g_e12[t] = e1 | (e2 << 8);
        g_g1[t] = inv;
        g_g2[t] = ed * inv;
        atomicAdd(&g_cnt[e1], 1);
        atomicAdd(&g_cnt[e2], 1);
    }
}

__global__ void zero_cnt_kernel() {
    if (threadIdx.x < NEXP) g_cnt[threadIdx.x] = 0;
}
__global__ void scan_kernel() {
    if (threadIdx.x == 0) {
        int s = 0;
        for (int e = 0; e < NEXP; e++) { g_off[e] = s; s += g_cnt[e]; g_fill[e] = 0; }
    }
}
__global__ void place_kernel() {
    int t = blockIdx.x * 256 + threadIdx.x;
    if (t >= N_TOK) return;
    int e12 = g_e12[t];
    int e1 = e12 & 0xFF, e2 = e12 >> 8;
    int s1 = g_off[e1] + atomicAdd(&g_fill[e1], 1);
    g_list[s1] = t; g_s1[t] = s1;
    int s2 = g_off[e2] + atomicAdd(&g_fill[e2], 1);
    g_list[s2] = t; g_s2[t] = s2;
}

// ---------------- final combine: out = x + g1*y[s1] + g2*y[s2] ------------------
__global__ void combine_kernel(const float* __restrict__ x, float* __restrict__ out) {
    int t = blockIdx.x;
    int s1 = g_s1[t], s2 = g_s2[t];
    float a = g_g1[t], b = g_g2[t];
    const float4* xr = (const float4*)(x   + (size_t)t  * DIM);
    const float4* y1 = (const float4*)(g_y + (size_t)s1 * DIM);
    const float4* y2 = (const float4*)(g_y + (size_t)s2 * DIM);
    float4* o = (float4*)(out + (size_t)t * DIM);
    int i = threadIdx.x;
    float4 xv = xr[i], v1 = y1[i], v2 = y2[i];
    float4 r;
    r.x = xv.x + a * v1.x + b * v2.x;
    r.y = xv.y + a * v1.y + b * v2.y;
    r.z = xv.z + a * v1.z + b * v2.z;
    r.w = xv.w + a * v1.w + b * v2.w;
    o[i] = r;
}

// ---------------- tf32 mma.sync GEMM (128x256 CTA, 64x64 warp tiles) ------------
// 3-stage cp.async pipeline, 1 CTA/SM (R4 proven config).
// MODE 0: g_hr = relu(split-tf32(xn @ r_w1) + b)       M=16384 N=2048 K=1024
// MODE 1: g_h  = rtf32(relu(gather(xn) @ e_w1 + b))    M=cnt   N=4096 K=1024
// MODE 2: g_y  = g_h @ e_w2 + b   (compact rows)       M=cnt   N=1024 K=4096
template <int MODE>
__global__ void __launch_bounds__(256, 1)
moe_mma(const float* __restrict__ Wbase, const float* __restrict__ Wlbase,
        const float* __restrict__ bias) {
    constexpr bool SPLIT = (MODE == 0);
    constexpr int Kd  = (MODE == 2) ? HID : DIM;
    constexpr int Nd  = (MODE == 0) ? HHALF : (MODE == 1) ? HID : DIM;
    constexpr int BKC = SPLIT ? 16 : 32;
    constexpr int NC  = Kd / BKC;
    constexpr int AST = BKC + 4;
    constexpr int ASZ = BM * AST;
    constexpr int BSZ = BKC * BSTRD;
    constexpr int STG = (SPLIT ? 2 : 1) * (ASZ + BSZ);
    constexpr int AJ  = BKC / 8;
    constexpr int BJ  = BKC / 4;

    int bm = blockIdx.y * BM, bn = blockIdx.x * BN;
    int e = 0, cnt = N_TOK, base = 0;
    if (MODE != 0) {
        e = blockIdx.z;
        cnt = g_cnt[e];
        if (bm >= cnt) return;
        base = g_off[e];
    }
    const float* Wh = (MODE == 0) ? Wbase
                    : (MODE == 1) ? Wbase + (size_t)e * DIM * HID
                                  : Wbase + (size_t)e * HID * DIM;
    const float* Wl = Wlbase;
    const float* bp = bias + ((MODE == 0) ? 0 : (MODE == 1) ? e * HID : e * DIM);

    extern __shared__ float sm[];
    uint32_t smb = smem_u32(sm);

    int tid = threadIdx.x, lane = tid & 31, wid = tid >> 5;
    int wm = (wid >> 2) * 64, wn = (wid & 3) * 64;

    // ---- per-thread load slots ----
    const float* ah[AJ];
    const float* al[AJ];
    const float* bh[BJ];
    const float* bl[BJ];
    uint32_t adst[AJ], bdst[BJ];
#pragma unroll
    for (int j = 0; j < AJ; j++) {
        int id = tid + 256 * j;
        int row = id / (BKC / 4), c4 = id % (BKC / 4);
        adst[j] = (uint32_t)row * (AST * 4) + c4 * 16;
        int r = bm + row;
        if (MODE == 1) {
            int rr = (r < cnt) ? r : cnt - 1;
            ah[j] = g_xn + (size_t)g_list[base + rr] * DIM + c4 * 4;
        } else if (MODE == 2) {
            int rr = (r < cnt) ? r : cnt - 1;
            ah[j] = g_h + (size_t)(base + rr) * HID + c4 * 4;
        } else {
            ah[j] = g_xn  + (size_t)r * DIM + c4 * 4;
            al[j] = g_xnl + (size_t)r * DIM + c4 * 4;
        }
    }
#pragma unroll
    for (int j = 0; j < BJ; j++) {
        int id = tid + 256 * j;
        int kr = id >> 6, c = id & 63;
        bdst[j] = (uint32_t)kr * (BSTRD * 4) + c * 16;
        bh[j] = Wh + (size_t)kr * Nd + bn + c * 4;
        if (SPLIT) bl[j] = Wl + (size_t)kr * Nd + bn + c * 4;
    }

    auto load = [&](int i, int st) {
        uint32_t s0 = smb + (uint32_t)st * STG * 4;
        uint32_t b0 = s0 + (SPLIT ? 2u : 1u) * ASZ * 4;
        int ko = i * BKC;
        size_t bko = (size_t)ko * Nd;
#pragma unroll
        for (int j = 0; j < AJ; j++) {
            CP16(s0 + adst[j], ah[j] + ko);
            if (SPLIT) CP16(s0 + ASZ * 4 + adst[j], al[j] + ko);
        }
#pragma unroll
        for (int j = 0; j < BJ; j++) {
            CP16(b0 + bdst[j], bh[j] + bko);
            if (SPLIT) CP16(b0 + BSZ * 4 + bdst[j], bl[j] + bko);
        }
        CP_COMMIT();
    };

    float c[4][8][4] = {};
    load(0, 0);
    load(1, 1);

    int lr = lane >> 2, lc = lane & 3;
    for (int i = 0; i < NC; i++) {
        int st = i % 3;
        if (i + 2 < NC) { CP_WAIT1(); } else { CP_WAIT0(); }
        __syncthreads();
        if (i + 2 < NC) load(i + 2, (i + 2) % 3);

        const uint32_t* Au = (const uint32_t*)(sm + st * STG);
        const uint32_t* Bu = Au + (SPLIT ? 2 : 1) * ASZ;
#pragma unroll
        for (int ks = 0; ks < BKC / 8; ks++) {
            uint32_t a[4][4], b[8][2];
#pragma unroll
            for (int mt = 0; mt < 4; mt++) {
                const uint32_t* ap = Au + (wm + mt * 16 + lr) * AST + ks * 8 + lc;
                a[mt][0] = ap[0];
                a[mt][1] = ap[8 * AST];
                a[mt][2] = ap[4];
                a[mt][3] = ap[8 * AST + 4];
            }
#pragma unroll
            for (int nt = 0; nt < 8; nt++) {
                const uint32_t* bpp = Bu + (ks * 8 + lc) * BSTRD + wn + nt * 8 + lr;
                b[nt][0] = bpp[0];
                b[nt][1] = bpp[4 * BSTRD];
            }
#pragma unroll
            for (int mt = 0; mt < 4; mt++)
#pragma unroll
                for (int nt = 0; nt < 8; nt++)
                    mma8(c[mt][nt], a[mt], b[nt]);
            if (SPLIT) {
                // hi * lo
                uint32_t t2[8][2];
#pragma unroll
                for (int nt = 0; nt < 8; nt++) {
                    const uint32_t* bpp = Bu + BSZ + (ks * 8 + lc) * BSTRD + wn + nt * 8 + lr;
                    t2[nt][0] = bpp[0];
                    t2[nt][1] = bpp[4 * BSTRD];
                }
#pragma unroll
                for (int mt = 0; mt < 4; mt++)
#pragma unroll
                    for (int nt = 0; nt < 8; nt++)
                        mma8(c[mt][nt], a[mt], t2[nt]);
                // lo * hi
                uint32_t a2[4][4];
#pragma unroll
                for (int mt = 0; mt < 4; mt++) {
                    const uint32_t* ap = Au + ASZ + (wm + mt * 16 + lr) * AST + ks * 8 + lc;
                    a2[mt][0] = ap[0];
                    a2[mt][1] = ap[8 * AST];
                    a2[mt][2] = ap[4];
                    a2[mt][3] = ap[8 * AST + 4];
                }
#pragma unroll
                for (int mt = 0; mt < 4; mt++)
#pragma unroll
                    for (int nt = 0; nt < 8; nt++)
                        mma8(c[mt][nt], a2[mt], b[nt]);
            }
        }
    }

    // ---------------- epilogue ----------------
#pragma unroll
    for (int mt = 0; mt < 4; mt++) {
#pragma unroll
        for (int half = 0; half < 2; half++) {
            int r = bm + wm + mt * 16 + lr + half * 8;
            if (MODE != 0 && r >= cnt) continue;
            float* row;
            if (MODE == 0)      row = g_hr + (size_t)r * HHALF;
            else if (MODE == 1) row = g_h  + (size_t)(base + r) * HID;
            else                row = g_y  + (size_t)(base + r) * DIM;
#pragma unroll
            for (int nt = 0; nt < 8; nt++) {
                int col = bn + wn + nt * 8 + lc * 2;
                float v0 = c[mt][nt][half * 2]     + bp[col];
                float v1 = c[mt][nt][half * 2 + 1] + bp[col + 1];
                float2 st2;
                if (MODE == 0) {
                    st2.x = fmaxf(v0, 0.f); st2.y = fmaxf(v1, 0.f);
                } else if (MODE == 1) {
                    st2.x = rtf32(fmaxf(v0, 0.f)); st2.y = rtf32(fmaxf(v1, 0.f));
                } else {
                    st2.x = v0; st2.y = v1;
                }
                *(float2*)(row + col) = st2;
            }
        }
    }
}

// ---------------- launch ---------------------------------------------------------
extern "C" void kernel_launch(void* const* d_in, const int* in_sizes, int n_in,
                              void* d_out, int out_size) {
    const float* x    = (const float*)d_in[0];
    const float* ln_g = (const float*)d_in[1];
    const float* ln_b = (const float*)d_in[2];
    const float* r_w1 = (const float*)d_in[3];
    const float* r_b1 = (const float*)d_in[4];
    const float* r_w2 = (const float*)d_in[5];
    const float* r_b2 = (const float*)d_in[6];
    const float* e_w1 = (const float*)d_in[7];
    const float* e_b1 = (const float*)d_in[8];
    const float* e_w2 = (const float*)d_in[9];
    const float* e_b2 = (const float*)d_in[10];
    float* out = (float*)d_out;

    // smem sizes (3-stage, R4 config)
    const int SMEM_P = 3 * (BM * 36 + 32 * BSTRD) * 4;             // plain: 156672
    const int SMEM_S = 3 * (2 * (BM * 20) + 2 * (16 * BSTRD)) * 4; // split: 162816

    static int configured = 0;
    if (!configured) {
        cudaFuncSetAttribute(moe_mma<0>, cudaFuncAttributeMaxDynamicSharedMemorySize, SMEM_S);
        cudaFuncSetAttribute(moe_mma<1>, cudaFuncAttributeMaxDynamicSharedMemorySize, SMEM_P);
        cudaFuncSetAttribute(moe_mma<2>, cudaFuncAttributeMaxDynamicSharedMemorySize, SMEM_P);
        configured = 1;
    }

    zero_cnt_kernel<<<1, 32>>>();
    ln_kernel<<<N_TOK, 256>>>(x, ln_g, ln_b);

    // router weight split (tf32 hi/lo)
    float *w1h, *w1l;
    cudaGetSymbolAddress((void**)&w1h, g_w1h);
    cudaGetSymbolAddress((void**)&w1l, g_w1l);
    split_copy<<<(DIM * HHALF / 4) / 256, 256>>>(r_w1, w1h, w1l);

    // router path (split-tf32 GEMM -> logits -> top-2 -> dispatch lists)
    moe_mma<0><<<dim3(HHALF / BN, N_TOK / BM), 256, SMEM_S>>>(w1h, w1l, r_b1);
    router_kernel<<<N_TOK / 8, 256>>>(r_w2, r_b2);
    scan_kernel<<<1, 32>>>();
    place_kernel<<<N_TOK / 256, 256>>>();

    // expert path (raw fp32 weights; HW truncates to tf32)
    moe_mma<1><<<dim3(HID / BN, N_TOK / BM, NEXP), 256, SMEM_P>>>(e_w1, nullptr, e_b1);
    moe_mma<2><<<dim3(DIM / BN, N_TOK / BM, NEXP), 256, SMEM_P>>>(e_w2, nullptr, e_b2);

    // out = x + g1*y1 + g2*y2
    combine_kernel<<<N_TOK, 256>>>(x, out);
}